// round 16
// baseline (speedup 1.0000x reference)
#include <cuda_runtime.h>
#include <math.h>

// BayesRingRNN collapses exactly to a 2-scalar recurrence per batch:
// r_i(t) = u(t)*cos(phi_i) + v(t)*sin(phi_i)   (rank-2 weights, r0 in span).
//
// Three-kernel graph pipeline:
//   1) transpose inputs (B,T) -> (T,B)            (~4us, coalesced tiles)
//   2) chain_slice x6: LANE-PARALLEL chains -- one lane = one batch, 32
//      warps total, no shuffles; ~35 cyc/step latency => ~5us per slice
//   3) expand_slice x6 on a side stream, gated by events; grid = 7 CTAs/SM
//      so one SM slot stays free and chain k+1 overlaps expand k.
// R15 bug fixed: prefetch ring slot is (t & 7) -- prologue must fill slot
// (t0+i)&7, not i, because SLICE=250 is not a multiple of 8.

#define NN 80
#define TT 1500
#define MAXB 1024
#define NS 6
#define SLICE (TT / NS)               // 250
#define PF 8                          // input prefetch depth (ring in regs)

__device__ float2 g_inT [(size_t)TT * MAXB];   // inputs, time-major (12.3 MB)
__device__ float2 g_trajT[(size_t)TT * MAXB];  // (u,v), time-major (12.3 MB)
__device__ float2 g_state[MAXB];               // (u,v) carried between slices

// ------------------------------------------------------------ transpose ---
__global__ void __launch_bounds__(256)
transpose_kernel(const float2* __restrict__ in, int B)   // in: (B,T)
{
    __shared__ float2 tile[32][33];
    const int bt = blockIdx.x * 32;   // t-block
    const int bb = blockIdx.y * 32;   // b-block
    const int tx = threadIdx.x, ty = threadIdx.y;  // 32 x 8

    #pragma unroll
    for (int k = 0; k < 32; k += 8) {
        const int b = bb + ty + k, t = bt + tx;
        if (b < B && t < TT) tile[ty + k][tx] = in[(size_t)b * TT + t];
    }
    __syncthreads();
    #pragma unroll
    for (int k = 0; k < 32; k += 8) {
        const int t = bt + ty + k, b = bb + tx;
        if (b < B && t < TT) g_inT[(size_t)t * B + b] = tile[tx][ty + k];
    }
}

// ---------------------------------------------------------- chain slice ---
// One lane = one batch. grid = B/32 CTAs x 32 threads (tiny footprint).
__global__ void __launch_bounds__(32)
chain_slice(const float* __restrict__ phi, float* __restrict__ out,
            int B, float kz, int t0, long long out_size)
{
    const int b = blockIdx.x * 32 + threadIdx.x;
    if (b >= B) return;

    const float C1 = 0.01f / 3.0f;   // DT/(KP+KV)
    const float C3 = 2.0f / 3.0f;    // a_odd

    float u, v;
    if (t0 == 0) { u = 10.0f; v = 0.0f; }           // r0 = 10*cos(phi)
    else         { float2 st = g_state[b]; u = st.x; v = st.y; }

    const int tend = t0 + SLICE;

    // register ring keyed by (t & 7): prologue fills slot (t0+i)&7 (FIX).
    float2 buf[PF];
    #pragma unroll
    for (int i = 0; i < PF; ++i) {
        const int t = t0 + i;
        buf[t & (PF - 1)] = (t < TT) ? g_inT[(size_t)t * B + b]
                                     : make_float2(0.f, 0.f);
    }

    #pragma unroll 4
    for (int t = t0; t < tend; ++t) {
        const float2 x = buf[t & (PF - 1)];
        const int tp = t + PF;
        if (tp < TT) buf[t & (PF - 1)] = g_inT[(size_t)tp * B + b];

        float s, co; sincosf(x.x, &s, &co);         // off the critical path
        const float kc = kz * co, ks = kz * s, gi = C3 * x.y;

        const float xx = fmaf(u, u, v * v);          // |z|^2 > 0 always
        const float y  = rsqrtf(xx);                 // MUFU.RSQ
        const float d  = fmaf(-(C1 * xx), y, 1.0f);
        const float nu = fmaf(d, u, fmaf(-gi, v, kc));
        const float nv = fmaf(d, v, fmaf( gi, u, ks));
        u = nu; v = nv;

        g_trajT[(size_t)t * B + b] = make_float2(u, v);   // coalesced 256B
    }

    g_state[b] = make_float2(u, v);

    // last slice also writes r_final (1,B,N) after the (B,T,N) block
    if (tend >= TT) {
        const long long base = (long long)B * TT * NN;
        if (out_size >= base + (long long)B * NN) {
            float* fp = out + base + (size_t)b * NN;
            #pragma unroll 4
            for (int i = 0; i < NN; ++i) {
                float s, c; sincosf(phi[i], &s, &c);
                fp[i] = fmaf(v, s, u * c);
            }
        }
    }
}

// --------------------------------------------------------- expand slice ---
// R2-proven bandwidth kernel, reading time-major traj. 7 CTAs/SM.
__global__ void __launch_bounds__(256)
expand_slice(const float* __restrict__ phi, float* __restrict__ out,
             int B, int t0)
{
    __shared__ float4 c4[NN / 4], s4[NN / 4];
    if (threadIdx.x < NN) {
        float s, c; sincosf(phi[threadIdx.x], &s, &c);
        reinterpret_cast<float*>(c4)[threadIdx.x] = c;
        reinterpret_cast<float*>(s4)[threadIdx.x] = s;
    }
    __syncthreads();

    float4* __restrict__ o4 = reinterpret_cast<float4*>(out);
    const int stride = gridDim.x * blockDim.x;
    const int total4 = B * SLICE * (NN / 4);

    for (int i = blockIdx.x * blockDim.x + threadIdx.x; i < total4; i += stride) {
        const int q   = i / (NN / 4);            // mul-shift
        const int n4  = i - q * (NN / 4);
        const int b   = q / SLICE;               // mul-shift (SLICE literal)
        const int tl  = q - b * SLICE;
        const float2 uv = g_trajT[(size_t)(t0 + tl) * B + b];   // L2-hot
        const float4 c = c4[n4];
        const float4 s = s4[n4];
        float4 o;
        o.x = fmaf(uv.y, s.x, uv.x * c.x);
        o.y = fmaf(uv.y, s.y, uv.x * c.y);
        o.z = fmaf(uv.y, s.z, uv.x * c.z);
        o.w = fmaf(uv.y, s.w, uv.x * c.w);
        o4[((size_t)b * TT + t0 + tl) * (NN / 4) + n4] = o;
    }
}

// --- host-side exact replica of the reference's _xi_inv (double precision) --
static double xi_f(double a, double target)
{
    const double x = (a / 2.0) * (a / 2.0);
    double t0 = 1.0, t1 = a / 2.0;
    double i0 = t0, i1 = t1;
    for (int k = 1; k < 30; ++k) {
        t0 *= x / ((double)k * (double)k);
        t1 *= x / ((double)k * (double)(k + 1));
        i0 += t0;
        i1 += t1;
    }
    return a * i1 / i0 - target;
}

static float compute_kappa_z()
{
    const double target = 15.0 * 0.01;
    double lo = 1e-3, hi = 50.0;
    for (int i = 0; i < 200; ++i) {
        const double mid = 0.5 * (lo + hi);
        if (xi_f(lo, target) * xi_f(mid, target) <= 0.0) hi = mid;
        else lo = mid;
    }
    return (float)(0.5 * (lo + hi));
}

extern "C" void kernel_launch(void* const* d_in, const int* in_sizes, int n_in,
                              void* d_out, int out_size)
{
    const float* inputs = (const float*)d_in[0];  // (B,T,2)
    const float* phi    = (const float*)d_in[4];  // (N,)
    float* out = (float*)d_out;

    int B = in_sizes[0] / (2 * TT);
    if (B > MAXB) B = MAXB;
    const float kz = compute_kappa_z();

    cudaStream_t s2;
    cudaStreamCreateWithFlags(&s2, cudaStreamNonBlocking);
    cudaEvent_t evC[NS], evFin;
    for (int k = 0; k < NS; ++k)
        cudaEventCreateWithFlags(&evC[k], cudaEventDisableTiming);
    cudaEventCreateWithFlags(&evFin, cudaEventDisableTiming);

    // 1) transpose inputs to time-major
    {
        dim3 grid((TT + 31) / 32, (B + 31) / 32);
        dim3 block(32, 8);
        transpose_kernel<<<grid, block>>>(
            reinterpret_cast<const float2*>(inputs), B);
    }

    // 2+3) sliced chain (stream 0) + expansion (s2), event-gated
    const int cblocks = (B + 31) / 32;            // 32 CTAs of 32 threads
    const int eblocks = 1036;                     // 7 CTAs/SM: leave a free slot
    for (int k = 0; k < NS; ++k) {
        chain_slice<<<cblocks, 32>>>(phi, out, B, kz, k * SLICE,
                                     (long long)out_size);
        cudaEventRecord(evC[k], 0);
        cudaStreamWaitEvent(s2, evC[k], 0);
        expand_slice<<<eblocks, 256, 0, s2>>>(phi, out, B, k * SLICE);
    }

    // join the side stream back into the default (captured) stream
    cudaEventRecord(evFin, s2);
    cudaStreamWaitEvent(0, evFin, 0);
}

// round 17
// speedup vs baseline: 5.6392x; 5.6392x over previous
#include <cuda_runtime.h>
#include <math.h>

// BayesRingRNN collapses exactly to a 2-scalar recurrence per batch:
// r_i(t) = u(t)*cos(phi_i) + v(t)*sin(phi_i)   (rank-2 weights, r0 in span).
//
// Serial two-kernel pipeline (overlap attempts 0/4 -- abandoned):
//   1) chain_kernel: warp-per-batch serial recurrence (rsqrt, shuffles --
//      the only chain variant ever measured fast), writes g_traj + r_final.
//   2) expand_kernel (LEAN): block=320 (divisible by 20) so n4=i%20 is
//      thread-invariant -> basis in registers, ZERO smem in the loop; and
//      out(B*T,20 float4) / traj(B*T float2) share bt order -> no divides:
//      just q += stride/20. Per-warp-iter L1 cost ~5 cyc vs R2's ~13
//      (2x LDS.128 removed), so stores run at the LTS cap instead of 5.5TB/s.

#define NN 80
#define TT 1500
#define MAXB 1024
#define CH 32

__device__ float2 g_traj[(size_t)MAXB * TT];   // 12.3 MB, (B,T) order

// ------------------------------------------------------------- chain ------
__global__ void __launch_bounds__(128, 8)
chain_kernel(const float* __restrict__ inputs,   // (B,T,2)
             const float* __restrict__ phi,      // (N,)
             float* __restrict__ out,            // tail: r_final (1,B,N)
             int B, float kz, long long out_size)
{
    const int b    = (blockIdx.x * blockDim.x + threadIdx.x) >> 5;
    const int lane = threadIdx.x & 31;
    if (b >= B) return;

    const float C1 = 0.01f / 3.0f;   // DT/(KP+KV)
    const float C3 = 2.0f / 3.0f;    // a_odd
    float u = 10.0f, v = 0.0f;       // r0 = 10*cos(phi) -> (10,0) exactly

    const float2* __restrict__ inp =
        reinterpret_cast<const float2*>(inputs) + (size_t)b * TT;
    float2* __restrict__ tr = g_traj + (size_t)b * TT;

    float2 nx = inp[lane];           // prefetch chunk 0

    for (int t = 0; t < TT; t += CH) {
        const int len = min(CH, TT - t);
        const float2 x = nx;
        if (t + CH + lane < TT) nx = inp[t + CH + lane];

        float kc = 0.f, ks = 0.f, gi = 0.f;
        if (lane < len) {
            float s, co; sincosf(x.x, &s, &co);
            kc = kz * co; ks = kz * s; gi = C3 * x.y;
        }
        float su = u, sv = v;
        #pragma unroll 4
        for (int j = 0; j < len; ++j) {
            const float gij = __shfl_sync(0xffffffffu, gi, j);
            const float kcj = __shfl_sync(0xffffffffu, kc, j);
            const float ksj = __shfl_sync(0xffffffffu, ks, j);

            const float xx = fmaf(u, u, v * v);   // |z|^2 > 0 always
            const float y  = rsqrtf(xx);          // MUFU.RSQ
            const float d  = fmaf(-(C1 * xx), y, 1.0f);
            const float nu = fmaf(d, u, fmaf(-gij, v, kcj));
            const float nv = fmaf(d, v, fmaf( gij, u, ksj));
            u = nu; v = nv;
            if (j == lane) { su = u; sv = v; }
        }
        if (lane < len) tr[t + lane] = make_float2(su, sv);   // coalesced 256B
    }

    // r_final (1,B,N) after the (B,T,N) block
    const long long base = (long long)B * TT * NN;
    if (out_size >= base + (long long)B * NN && lane < NN / 4) {
        float4 c4, s4;
        sincosf(phi[4 * lane + 0], &s4.x, &c4.x);
        sincosf(phi[4 * lane + 1], &s4.y, &c4.y);
        sincosf(phi[4 * lane + 2], &s4.z, &c4.z);
        sincosf(phi[4 * lane + 3], &s4.w, &c4.w);
        float4 o;
        o.x = fmaf(v, s4.x, u * c4.x);
        o.y = fmaf(v, s4.y, u * c4.y);
        o.z = fmaf(v, s4.z, u * c4.z);
        o.w = fmaf(v, s4.w, u * c4.w);
        reinterpret_cast<float4*>(out + base + (size_t)b * NN)[lane] = o;
    }
}

// ------------------------------------------------------------- expand -----
// block = 320 => stride % 20 == 0 => n4 fixed per thread, q advances by
// stride/20. Loop body: LDG.64 (L2-hot traj) + 8 FMA + STG.128. No smem,
// no divides, no bt decomposition (out and traj share bt order).
__global__ void __launch_bounds__(320)
expand_kernel(const float* __restrict__ phi, float* __restrict__ out,
              int total4)
{
    const int i0 = blockIdx.x * 320 + threadIdx.x;
    const int n4 = i0 % 20;                       // one-time division

    float4 cc, ss;                                // basis in registers
    sincosf(phi[4 * n4 + 0], &ss.x, &cc.x);
    sincosf(phi[4 * n4 + 1], &ss.y, &cc.y);
    sincosf(phi[4 * n4 + 2], &ss.z, &cc.z);
    sincosf(phi[4 * n4 + 3], &ss.w, &cc.w);

    float4* __restrict__ o4 = reinterpret_cast<float4*>(out);
    const int stride  = gridDim.x * 320;          // always % 20 == 0
    const int qstride = stride / 20;

    int q = i0 / 20;
    #pragma unroll 2
    for (int i = i0; i < total4; i += stride, q += qstride) {
        const float2 uv = g_traj[q];              // L2-hot (just written)
        float4 o;
        o.x = fmaf(uv.y, ss.x, uv.x * cc.x);
        o.y = fmaf(uv.y, ss.y, uv.x * cc.y);
        o.z = fmaf(uv.y, ss.z, uv.x * cc.z);
        o.w = fmaf(uv.y, ss.w, uv.x * cc.w);
        __stcs(&o4[i], o);
    }
}

// --- host-side exact replica of the reference's _xi_inv (double precision) --
static double xi_f(double a, double target)
{
    const double x = (a / 2.0) * (a / 2.0);
    double t0 = 1.0, t1 = a / 2.0;
    double i0 = t0, i1 = t1;
    for (int k = 1; k < 30; ++k) {
        t0 *= x / ((double)k * (double)k);
        t1 *= x / ((double)k * (double)(k + 1));
        i0 += t0;
        i1 += t1;
    }
    return a * i1 / i0 - target;
}

static float compute_kappa_z()
{
    const double target = 15.0 * 0.01;
    double lo = 1e-3, hi = 50.0;
    for (int i = 0; i < 200; ++i) {
        const double mid = 0.5 * (lo + hi);
        if (xi_f(lo, target) * xi_f(mid, target) <= 0.0) hi = mid;
        else lo = mid;
    }
    return (float)(0.5 * (lo + hi));
}

extern "C" void kernel_launch(void* const* d_in, const int* in_sizes, int n_in,
                              void* d_out, int out_size)
{
    const float* inputs = (const float*)d_in[0];  // (B,T,2)
    const float* phi    = (const float*)d_in[4];  // (N,)
    float* out = (float*)d_out;

    int B = in_sizes[0] / (2 * TT);
    if (B > MAXB) B = MAXB;
    const float kz = compute_kappa_z();

    // 1) chains (warp-per-batch, latency-bound, ~25us)
    {
        const int blocks = (B * 32 + 127) / 128;
        chain_kernel<<<blocks, 128>>>(inputs, phi, out, B, kz,
                                      (long long)out_size);
    }
    // 2) lean expansion (store-bound)
    {
        const int total4 = B * TT * (NN / 4);     // 30.72M float4
        expand_kernel<<<740, 320>>>(phi, out, total4);   // 5 CTAs/SM
    }
}